// round 2
// baseline (speedup 1.0000x reference)
#include <cuda_runtime.h>

// TriplesDistances: B=16, N=512, A=1024
// inputs: positions f32 [B,N,3]; neighbors_j/k int32 [B,N,A]  (JAX x64 disabled)
// out layout: [r_ij | r_ik | r_jk], each B*N*A float32
#define NB 16
#define NN 512
#define NA 1024
#define THREADS 256

__device__ __forceinline__ float dist3(float4 a, float4 b) {
    float dx = a.x - b.x;
    float dy = a.y - b.y;
    float dz = a.z - b.z;
    float s = fmaf(dx, dx, fmaf(dy, dy, dz * dz));
    return (s > 0.0f) ? sqrtf(s) : 0.0f;
}

__global__ __launch_bounds__(THREADS)
void TriplesDistances_kernel(const float* __restrict__ pos,
                             const int* __restrict__ nj,
                             const int* __restrict__ nk,
                             float* __restrict__ out) {
    __shared__ float4 sp[NN];  // 8 KB: positions of this batch, padded float4

    const int bn = blockIdx.x;       // b*NN + n
    const int b  = bn >> 9;          // NN = 512
    const int n  = bn & (NN - 1);

    // Cooperative stage of batch-b positions into smem
    const float* pb = pos + (size_t)b * NN * 3;
    #pragma unroll
    for (int i = threadIdx.x; i < NN; i += THREADS) {
        float x = pb[i * 3 + 0];
        float y = pb[i * 3 + 1];
        float z = pb[i * 3 + 2];
        sp[i] = make_float4(x, y, z, 0.0f);
    }
    __syncthreads();

    const float4 pi = sp[n];

    const size_t base  = (size_t)bn * NA;
    const size_t total = (size_t)NB * NN * NA;

    // Each thread: 4 consecutive a (256 threads * 4 = 1024 = NA)
    const int a0 = threadIdx.x * 4;

    const int4 j4 = *reinterpret_cast<const int4*>(nj + base + a0);
    const int4 k4 = *reinterpret_cast<const int4*>(nk + base + a0);

    float4 pj0 = sp[j4.x];
    float4 pj1 = sp[j4.y];
    float4 pj2 = sp[j4.z];
    float4 pj3 = sp[j4.w];
    float4 pk0 = sp[k4.x];
    float4 pk1 = sp[k4.y];
    float4 pk2 = sp[k4.z];
    float4 pk3 = sp[k4.w];

    float4 rij, rik, rjk;
    rij.x = dist3(pj0, pi);  rik.x = dist3(pk0, pi);  rjk.x = dist3(pj0, pk0);
    rij.y = dist3(pj1, pi);  rik.y = dist3(pk1, pi);  rjk.y = dist3(pj1, pk1);
    rij.z = dist3(pj2, pi);  rik.z = dist3(pk2, pi);  rjk.z = dist3(pj2, pk2);
    rij.w = dist3(pj3, pi);  rik.w = dist3(pk3, pi);  rjk.w = dist3(pj3, pk3);

    float4* o_ij = reinterpret_cast<float4*>(out + base + a0);
    float4* o_ik = reinterpret_cast<float4*>(out + total + base + a0);
    float4* o_jk = reinterpret_cast<float4*>(out + 2 * total + base + a0);
    o_ij[0] = rij;
    o_ik[0] = rik;
    o_jk[0] = rjk;
}

extern "C" void kernel_launch(void* const* d_in, const int* in_sizes, int n_in,
                              void* d_out, int out_size) {
    const float* pos = (const float*)d_in[0];
    const int*   nj  = (const int*)d_in[1];
    const int*   nk  = (const int*)d_in[2];
    float* out = (float*)d_out;

    dim3 grid(NB * NN);
    TriplesDistances_kernel<<<grid, THREADS>>>(pos, nj, nk, out);
}

// round 3
// speedup vs baseline: 1.1222x; 1.1222x over previous
#include <cuda_runtime.h>

// TriplesDistances: B=16, N=512, A=1024
// inputs: positions f32 [B,N,3]; neighbors_j/k int32 [B,N,A]
// out layout: [r_ij | r_ik | r_jk], each B*N*A float32
#define NB 16
#define NN 512
#define NA 1024
#define THREADS 256
#define ROWS 4   // rows (n values) per block, same batch

__device__ __forceinline__ float dist3(float4 a, float4 b) {
    float dx = a.x - b.x;
    float dy = a.y - b.y;
    float dz = a.z - b.z;
    float s = fmaf(dx, dx, fmaf(dy, dy, dz * dz));
    return (s > 0.0f) ? sqrtf(s) : 0.0f;
}

__global__ __launch_bounds__(THREADS, 4)
void TriplesDistances_kernel(const float* __restrict__ pos,
                             const int* __restrict__ nj,
                             const int* __restrict__ nk,
                             float* __restrict__ out) {
    __shared__ float4 sp[NN];  // 8 KB: positions of this batch

    const int blk = blockIdx.x;                 // 0 .. NB*NN/ROWS-1
    const int b   = blk / (NN / ROWS);          // batch
    const int n0  = (blk % (NN / ROWS)) * ROWS; // first row in batch

    // Cooperative stage of batch-b positions into smem (once per ROWS rows)
    const float* pb = pos + (size_t)b * NN * 3;
    #pragma unroll
    for (int i = threadIdx.x; i < NN; i += THREADS) {
        float x = pb[i * 3 + 0];
        float y = pb[i * 3 + 1];
        float z = pb[i * 3 + 2];
        sp[i] = make_float4(x, y, z, 0.0f);
    }
    __syncthreads();

    const size_t total = (size_t)NB * NN * NA;
    const int a0 = threadIdx.x * 4;
    const size_t base0 = ((size_t)b * NN + n0) * NA + a0;

    // Prefetch row 0 indices
    int4 j4 = *reinterpret_cast<const int4*>(nj + base0);
    int4 k4 = *reinterpret_cast<const int4*>(nk + base0);

    #pragma unroll
    for (int r = 0; r < ROWS; r++) {
        const size_t base = base0 + (size_t)r * NA;
        const int4 jc = j4, kc = k4;

        // Prefetch next row's indices while gathers are in flight
        if (r + 1 < ROWS) {
            j4 = *reinterpret_cast<const int4*>(nj + base + NA);
            k4 = *reinterpret_cast<const int4*>(nk + base + NA);
        }

        const float4 pi = sp[n0 + r];

        float4 pj0 = sp[jc.x];
        float4 pj1 = sp[jc.y];
        float4 pj2 = sp[jc.z];
        float4 pj3 = sp[jc.w];
        float4 pk0 = sp[kc.x];
        float4 pk1 = sp[kc.y];
        float4 pk2 = sp[kc.z];
        float4 pk3 = sp[kc.w];

        float4 rij, rik, rjk;
        rij.x = dist3(pj0, pi);  rik.x = dist3(pk0, pi);  rjk.x = dist3(pj0, pk0);
        rij.y = dist3(pj1, pi);  rik.y = dist3(pk1, pi);  rjk.y = dist3(pj1, pk1);
        rij.z = dist3(pj2, pi);  rik.z = dist3(pk2, pi);  rjk.z = dist3(pj2, pk2);
        rij.w = dist3(pj3, pi);  rik.w = dist3(pk3, pi);  rjk.w = dist3(pj3, pk3);

        *reinterpret_cast<float4*>(out + base)             = rij;
        *reinterpret_cast<float4*>(out + total + base)     = rik;
        *reinterpret_cast<float4*>(out + 2 * total + base) = rjk;
    }
}

extern "C" void kernel_launch(void* const* d_in, const int* in_sizes, int n_in,
                              void* d_out, int out_size) {
    const float* pos = (const float*)d_in[0];
    const int*   nj  = (const int*)d_in[1];
    const int*   nk  = (const int*)d_in[2];
    float* out = (float*)d_out;

    dim3 grid(NB * NN / ROWS);
    TriplesDistances_kernel<<<grid, THREADS>>>(pos, nj, nk, out);
}

// round 4
// speedup vs baseline: 1.1702x; 1.0428x over previous
#include <cuda_runtime.h>

// TriplesDistances: B=16, N=512, A=1024
// inputs: positions f32 [B,N,3]; neighbors_j/k int32 [B,N,A]
// out layout: [r_ij | r_ik | r_jk], each B*N*A float32
#define NB 16
#define NN 512
#define NA 1024
#define THREADS 256
#define ROWS 4   // rows (n values) per block, same batch

__device__ __forceinline__ float dist3(float4 a, float4 b) {
    float dx = a.x - b.x;
    float dy = a.y - b.y;
    float dz = a.z - b.z;
    float s = fmaf(dx, dx, fmaf(dy, dy, dz * dz));
    return (s > 0.0f) ? sqrtf(s) : 0.0f;
}

__global__ __launch_bounds__(THREADS, 5)
void TriplesDistances_kernel(const float* __restrict__ pos,
                             const int* __restrict__ nj,
                             const int* __restrict__ nk,
                             float* __restrict__ out) {
    __shared__ float4 sp[NN];  // 8 KB: positions of this batch

    const int blk = blockIdx.x;                 // 0 .. NB*NN/ROWS-1
    const int b   = blk / (NN / ROWS);          // batch
    const int n0  = (blk % (NN / ROWS)) * ROWS; // first row in batch

    // Cooperative stage of batch-b positions into smem (once per ROWS rows)
    const float* pb = pos + (size_t)b * NN * 3;
    #pragma unroll
    for (int i = threadIdx.x; i < NN; i += THREADS) {
        float x = pb[i * 3 + 0];
        float y = pb[i * 3 + 1];
        float z = pb[i * 3 + 2];
        sp[i] = make_float4(x, y, z, 0.0f);
    }
    __syncthreads();

    const size_t total = (size_t)NB * NN * NA;
    const int a0 = threadIdx.x * 4;
    const size_t base0 = ((size_t)b * NN + n0) * NA + a0;

    #pragma unroll
    for (int r = 0; r < ROWS; r++) {
        const size_t base = base0 + (size_t)r * NA;

        const int4 jc = *reinterpret_cast<const int4*>(nj + base);
        const int4 kc = *reinterpret_cast<const int4*>(nk + base);

        const float4 pi = sp[n0 + r];

        float4 rij, rik, rjk;

        // Pair 0+1: only 4 float4 gathers live at once (register pressure)
        {
            float4 pj0 = sp[jc.x];
            float4 pk0 = sp[kc.x];
            float4 pj1 = sp[jc.y];
            float4 pk1 = sp[kc.y];
            rij.x = dist3(pj0, pi);  rik.x = dist3(pk0, pi);  rjk.x = dist3(pj0, pk0);
            rij.y = dist3(pj1, pi);  rik.y = dist3(pk1, pi);  rjk.y = dist3(pj1, pk1);
        }
        // Pair 2+3
        {
            float4 pj2 = sp[jc.z];
            float4 pk2 = sp[kc.z];
            float4 pj3 = sp[jc.w];
            float4 pk3 = sp[kc.w];
            rij.z = dist3(pj2, pi);  rik.z = dist3(pk2, pi);  rjk.z = dist3(pj2, pk2);
            rij.w = dist3(pj3, pi);  rik.w = dist3(pk3, pi);  rjk.w = dist3(pj3, pk3);
        }

        *reinterpret_cast<float4*>(out + base)             = rij;
        *reinterpret_cast<float4*>(out + total + base)     = rik;
        *reinterpret_cast<float4*>(out + 2 * total + base) = rjk;
    }
}

extern "C" void kernel_launch(void* const* d_in, const int* in_sizes, int n_in,
                              void* d_out, int out_size) {
    const float* pos = (const float*)d_in[0];
    const int*   nj  = (const int*)d_in[1];
    const int*   nk  = (const int*)d_in[2];
    float* out = (float*)d_out;

    dim3 grid(NB * NN / ROWS);
    TriplesDistances_kernel<<<grid, THREADS>>>(pos, nj, nk, out);
}

// round 5
// speedup vs baseline: 1.3333x; 1.1394x over previous
#include <cuda_runtime.h>

// TriplesDistances: B=16, N=512, A=1024
// inputs: positions f32 [B,N,3]; neighbors_j/k int32 [B,N,A]
// out layout: [r_ij | r_ik | r_jk], each B*N*A float32
#define NB 16
#define NN 512
#define NA 1024
#define THREADS 256
#define ROWS 4   // rows (n values) per block, same batch

__device__ __forceinline__ float dist3(float2 axy, float az, float2 bxy, float bz) {
    float dx = axy.x - bxy.x;
    float dy = axy.y - bxy.y;
    float dz = az - bz;
    float s = fmaf(dx, dx, fmaf(dy, dy, dz * dz));
    // s * rsqrt(s) == sqrt(s); select handles s==0 (0*inf=NaN -> 0)
    float r = s * rsqrtf(s);
    return (s > 0.0f) ? r : 0.0f;
}

__global__ __launch_bounds__(THREADS, 5)
void TriplesDistances_kernel(const float* __restrict__ pos,
                             const int* __restrict__ nj,
                             const int* __restrict__ nk,
                             float* __restrict__ out) {
    __shared__ float2 spxy[NN];  // 4 KB
    __shared__ float  spz[NN];   // 2 KB

    const int blk = blockIdx.x;                 // 0 .. NB*NN/ROWS-1
    const int b   = blk / (NN / ROWS);          // batch
    const int n0  = (blk % (NN / ROWS)) * ROWS; // first row in batch

    // Cooperative stage of batch-b positions into smem (SoA)
    const float* pb = pos + (size_t)b * NN * 3;
    #pragma unroll
    for (int i = threadIdx.x; i < NN; i += THREADS) {
        float x = pb[i * 3 + 0];
        float y = pb[i * 3 + 1];
        float z = pb[i * 3 + 2];
        spxy[i] = make_float2(x, y);
        spz[i]  = z;
    }
    __syncthreads();

    const size_t total = (size_t)NB * NN * NA;
    const int a0 = threadIdx.x * 4;
    const size_t base0 = ((size_t)b * NN + n0) * NA + a0;

    // Prefetch row 0 indices
    int4 j4 = *reinterpret_cast<const int4*>(nj + base0);
    int4 k4 = *reinterpret_cast<const int4*>(nk + base0);

    #pragma unroll
    for (int r = 0; r < ROWS; r++) {
        const size_t base = base0 + (size_t)r * NA;
        const int4 jc = j4, kc = k4;

        // Prefetch next row's indices while current gathers are in flight
        if (r + 1 < ROWS) {
            j4 = *reinterpret_cast<const int4*>(nj + base + NA);
            k4 = *reinterpret_cast<const int4*>(nk + base + NA);
        }

        const float2 pixy = spxy[n0 + r];
        const float  piz  = spz[n0 + r];

        float4 rij, rik, rjk;

        // Pair 0+1 (limit live gather temporaries)
        {
            float2 pj0 = spxy[jc.x]; float pj0z = spz[jc.x];
            float2 pk0 = spxy[kc.x]; float pk0z = spz[kc.x];
            float2 pj1 = spxy[jc.y]; float pj1z = spz[jc.y];
            float2 pk1 = spxy[kc.y]; float pk1z = spz[kc.y];
            rij.x = dist3(pj0, pj0z, pixy, piz);
            rik.x = dist3(pk0, pk0z, pixy, piz);
            rjk.x = dist3(pj0, pj0z, pk0, pk0z);
            rij.y = dist3(pj1, pj1z, pixy, piz);
            rik.y = dist3(pk1, pk1z, pixy, piz);
            rjk.y = dist3(pj1, pj1z, pk1, pk1z);
        }
        // Pair 2+3
        {
            float2 pj2 = spxy[jc.z]; float pj2z = spz[jc.z];
            float2 pk2 = spxy[kc.z]; float pk2z = spz[kc.z];
            float2 pj3 = spxy[jc.w]; float pj3z = spz[jc.w];
            float2 pk3 = spxy[kc.w]; float pk3z = spz[kc.w];
            rij.z = dist3(pj2, pj2z, pixy, piz);
            rik.z = dist3(pk2, pk2z, pixy, piz);
            rjk.z = dist3(pj2, pj2z, pk2, pk2z);
            rij.w = dist3(pj3, pj3z, pixy, piz);
            rik.w = dist3(pk3, pk3z, pixy, piz);
            rjk.w = dist3(pj3, pj3z, pk3, pk3z);
        }

        *reinterpret_cast<float4*>(out + base)             = rij;
        *reinterpret_cast<float4*>(out + total + base)     = rik;
        *reinterpret_cast<float4*>(out + 2 * total + base) = rjk;
    }
}

extern "C" void kernel_launch(void* const* d_in, const int* in_sizes, int n_in,
                              void* d_out, int out_size) {
    const float* pos = (const float*)d_in[0];
    const int*   nj  = (const int*)d_in[1];
    const int*   nk  = (const int*)d_in[2];
    float* out = (float*)d_out;

    dim3 grid(NB * NN / ROWS);
    TriplesDistances_kernel<<<grid, THREADS>>>(pos, nj, nk, out);
}